// round 3
// baseline (speedup 1.0000x reference)
#include <cuda_runtime.h>
#include <cuda_bf16.h>
#include <cstdint>

// MaxUnpooling2DMod: out[b, y(idx), x(idx), c] += in[b,h,w,c]
//   in  [8,128,128,64] -> 2^23 floats, out [8,256,256,64] -> 2^25 floats
// decode: out_off = (b << 22) + (idx & ~63) + (lin & 63)
//
// Pipeline (batch PAIRS): kernel k_p scatters batches {2p,2p+1} into slabs
// {2p,2p+1} (zeroed by previous kernel -> L2-hot atomics) and zeros slabs
// {2p+2,2p+3} under the atomic-bound scatter. 4 kernels + 1 memset prologue.

static constexpr int BLOCK   = 256;
static constexpr int GRID    = 2048;
static constexpr int THREADS = GRID * BLOCK;                 // 524288
static constexpr int ELEMS_PER_PAIR = 1 << 21;               // 2 batches of 2^20
static constexpr int PAIR_SLAB_F4   = (1 << 23) / 4;         // 2 slabs, in float4
static constexpr int ZERO_F4_PER_T  = PAIR_SLAB_F4 / THREADS; // 4

__global__ void __launch_bounds__(BLOCK)
unpool_pair_kernel(const float* __restrict__ in,
                   const int*   __restrict__ idx,
                   float*       __restrict__ out,
                   int p,        // batch pair to scatter (0..3)
                   int zp)       // slab pair to zero (-1 = none)
{
    const int t  = blockIdx.x * BLOCK + threadIdx.x;
    const int e0 = p * ELEMS_PER_PAIR + t * 4;       // 4 consecutive elems, same batch

    // Long-latency streaming loads first (evict-first: don't pollute L2,
    // the output slabs need the capacity).
    const float4 v  = __ldcs(reinterpret_cast<const float4*>(in)  + (e0 >> 2));
    const int4   id = __ldcs(reinterpret_cast<const int4*>(idx)   + (e0 >> 2));

    // Zero the NEXT slab pair (disjoint range -> no ordering hazard).
    if (zp >= 0) {
        float4* o4 = reinterpret_cast<float4*>(out) + (size_t)zp * PAIR_SLAB_F4;
        const float4 z = make_float4(0.f, 0.f, 0.f, 0.f);
        #pragma unroll
        for (int j = 0; j < ZERO_F4_PER_T; j++)
            o4[t + j * THREADS] = z;
    }

    // Scatter: 4 REDG into L2-hot slab.
    const int base = (e0 >> 20) << 22;               // batch slab base
    const int c0   = e0 & 63;                        // channel of elem 0 (mult of 4)
    atomicAdd(out + base + (id.x & ~63) + (c0 + 0), v.x);
    atomicAdd(out + base + (id.y & ~63) + (c0 + 1), v.y);
    atomicAdd(out + base + (id.z & ~63) + (c0 + 2), v.z);
    atomicAdd(out + base + (id.w & ~63) + (c0 + 3), v.w);
}

extern "C" void kernel_launch(void* const* d_in, const int* in_sizes, int n_in,
                              void* d_out, int out_size)
{
    const float* in  = (const float*)d_in[0];
    const int*   idx = (const int*)d_in[1];
    float*       out = (float*)d_out;

    // Prologue: zero slab pair 0 (batches 0,1) = first 2^23 floats.
    cudaMemsetAsync(out, 0, (size_t)(1 << 23) * sizeof(float), 0);

    for (int pr = 0; pr < 4; pr++)
        unpool_pair_kernel<<<GRID, BLOCK>>>(in, idx, out, pr, pr < 3 ? pr + 1 : -1);
}

// round 4
// speedup vs baseline: 1.4772x; 1.4772x over previous
#include <cuda_runtime.h>
#include <cuda_bf16.h>
#include <cstdint>

// MaxUnpooling2DMod: out[b, y(idx), x(idx), c] += in[b,h,w,c]
//   in  [8,128,128,64] -> 2^23 floats, out [8,256,256,64] -> 2^25 floats
// decode: out_off = (b << 22) + (idx & ~63) + (lin & 63)
//
// PDL-pipelined per-batch chain: kernel b scatters batch b into slab b
// (zeroed by kernel b-1) and zeros slab b+1. launch_dependents fires right
// after the zero stores, so kernel b+1 overlaps kernel b's atomic drain.

static constexpr int BLOCK        = 256;
static constexpr int GRID         = 1024;
static constexpr int THREADS      = GRID * BLOCK;          // 262144
static constexpr int SLAB_F4      = (1 << 22) / 4;         // 1,048,576 float4 per slab
static constexpr int ZERO_PER_T   = SLAB_F4 / THREADS;     // 4

__global__ void __launch_bounds__(BLOCK)
unpool_pdl_kernel(const float* __restrict__ in,
                  const int*   __restrict__ idx,
                  float*       __restrict__ out,
                  int bs,     // batch to scatter (-1 = none)
                  int bz)     // slab to zero    (-1 = none)
{
    const int t = blockIdx.x * BLOCK + threadIdx.x;

    // Streaming loads first — independent of the predecessor, get them in
    // flight before we block on griddepcontrol.wait.
    float4 v;
    int4   id;
    int    e0 = 0;
    if (bs >= 0) {
        e0 = (bs << 20) + (t << 2);
        v  = __ldcs(reinterpret_cast<const float4*>(in)  + (e0 >> 2));
        id = __ldcs(reinterpret_cast<const int4*>(idx)   + (e0 >> 2));
    }

    // Wait for predecessor's zero stores (our scatter slab) to be visible.
    asm volatile("griddepcontrol.wait;" ::: "memory");

    // Zero the NEXT slab (disjoint from every concurrently-active range).
    if (bz >= 0) {
        float4* o4 = reinterpret_cast<float4*>(out) + (size_t)bz * SLAB_F4;
        const float4 z = make_float4(0.f, 0.f, 0.f, 0.f);
        #pragma unroll
        for (int j = 0; j < ZERO_PER_T; j++)
            o4[t + j * THREADS] = z;
    }

    // Release the dependent kernel: its slab is now zeroed.
    asm volatile("griddepcontrol.launch_dependents;" ::: "memory");

    // Atomic scatter into slab bs (L2-hot: zeroed by predecessor).
    if (bs >= 0) {
        const int base = bs << 22;
        const int c0   = e0 & 63;          // elems e0..e0+3 share the 64-chan group
        atomicAdd(out + base + (id.x & ~63) + (c0 + 0), v.x);
        atomicAdd(out + base + (id.y & ~63) + (c0 + 1), v.y);
        atomicAdd(out + base + (id.z & ~63) + (c0 + 2), v.z);
        atomicAdd(out + base + (id.w & ~63) + (c0 + 3), v.w);
    }
}

extern "C" void kernel_launch(void* const* d_in, const int* in_sizes, int n_in,
                              void* d_out, int out_size)
{
    const float* in  = (const float*)d_in[0];
    const int*   idx = (const int*)d_in[1];
    float*       out = (float*)d_out;

    cudaLaunchAttribute attrs[1];
    attrs[0].id = cudaLaunchAttributeProgrammaticStreamSerialization;
    attrs[0].val.programmaticStreamSerializationAllowed = 1;

    cudaLaunchConfig_t cfg = {};
    cfg.gridDim  = dim3(GRID, 1, 1);
    cfg.blockDim = dim3(BLOCK, 1, 1);
    cfg.dynamicSmemBytes = 0;
    cfg.stream = 0;

    // Prologue: zero slab 0 only (no PDL attribute needed on the first launch).
    cfg.attrs = nullptr;
    cfg.numAttrs = 0;
    cudaLaunchKernelEx(&cfg, unpool_pdl_kernel, in, idx, out, -1, 0);

    // Pipelined chain: each launch may start as soon as its predecessor
    // executes launch_dependents (i.e., right after the zero stores).
    cfg.attrs = attrs;
    cfg.numAttrs = 1;
    for (int b = 0; b < 8; b++)
        cudaLaunchKernelEx(&cfg, unpool_pdl_kernel, in, idx, out,
                           b, b < 7 ? b + 1 : -1);
}